// round 15
// baseline (speedup 1.0000x reference)
#include <cuda_runtime.h>

#define NTHREADS 512
#define SAMPLES  32
#define HDIM     50
#define G4       256           // 64 units * 4 gates, cols 4j+g
#define TSTEPS   256
#define HROW     36            // floats per h row [k][s0..s31] + 4 pad (16B-aligned)
#define HBUF     (50*HROW)
#define XROW     36
#define XBUF     (32*XROW)

typedef unsigned long long ull;

__device__ __forceinline__ ull pack2(float lo, float hi) {
    ull r; asm("mov.b64 %0, {%1,%2};" : "=l"(r) : "f"(lo), "f"(hi)); return r;
}
__device__ __forceinline__ void unpack2(ull v, float& lo, float& hi) {
    asm("mov.b64 {%0,%1}, %2;" : "=f"(lo), "=f"(hi) : "l"(v));
}
__device__ __forceinline__ ull fma2(ull a, ull b, ull c) {
    ull d; asm("fma.rn.f32x2 %0, %1, %2, %3;" : "=l"(d) : "l"(a), "l"(b), "l"(c)); return d;
}
// HW tanh: 1 MUFU op
__device__ __forceinline__ float tanh_fast(float x) {
    float y; asm("tanh.approx.f32 %0, %1;" : "=f"(y) : "f"(x)); return y;
}
__device__ __forceinline__ float sigmoid_fast(float x) {
    return fmaf(0.5f, tanh_fast(0.5f * x), 0.5f);
}
// exact versions for the head
__device__ __forceinline__ float sigmoidf_(float x) {
    return __fdividef(1.f, 1.f + __expf(-x));
}
__device__ __forceinline__ float tanhf_(float x) {
    return fmaf(2.f, sigmoidf_(2.f * x), -1.f);
}
__device__ __forceinline__ void cohort_bar(int id) {
    asm volatile("bar.sync %0, %1;" :: "r"(id), "r"(128) : "memory");
}

// Dynamic shared layout (floats):
//  Ws  [51*256] : rows 0..49 = W_hh (col c=4j+g), row 50 = W_ih; zeros j>=50
//  bbv [256]    : b_ih + b_hh (col 4j+g)
//  hb  [2*50*36]: double-buffered hidden state, rows [k][s]
//  xs  [2*32*36]: double-buffered x tiles, rows [tt][s]
//  pad [32]     : dead sink for stagger chain
#define OFF_WS  0
#define OFF_BB  (51*G4)
#define OFF_HB  (OFF_BB + G4)
#define OFF_XS  (OFF_HB + 2*HBUF)
#define OFF_PAD (OFF_XS + 2*XBUF)
#define SMEM_FLOATS (OFF_PAD + 32)

__global__ void __launch_bounds__(NTHREADS, 1) lstm_q_kernel(
    const float* __restrict__ x,    const float* __restrict__ W_ih,
    const float* __restrict__ W_hh, const float* __restrict__ b_ih,
    const float* __restrict__ b_hh, const float* __restrict__ Wp,
    const float* __restrict__ bp,   const float* __restrict__ qw,
    const float* __restrict__ Wo,   const float* __restrict__ bo,
    float* __restrict__ out)
{
    extern __shared__ float sm[];
    float* Ws  = sm + OFF_WS;
    float* bbv = sm + OFF_BB;
    float* hb  = sm + OFF_HB;
    float* xs  = sm + OFF_XS;

    const int tid   = threadIdx.x;
    const int lane  = tid & 31;
    const int warp  = tid >> 5;
    const int coh   = warp >> 2;           // 4 cohorts: warps {4c..4c+3}; SMSP = warp&3
    const int ctid  = tid & 127;           // thread id within cohort
    const int ug    = warp & 1;            // unit group (0..1)
    const int sg    = (warp >> 1) & 1;     // sample group within cohort (0..1)
    const int j     = 32 * ug + lane;      // this thread's hidden unit (0..63)
    const bool jv   = (j < HDIM);          // valid-unit predicate
    const int sb    = 8 * coh + 4 * sg;    // first of 4 samples
    const int bbase = blockIdx.x * SAMPLES;
    const int bid   = coh + 1;             // named barrier id (1..4), 128 threads

    // ---- stage weights into shared (whole block) ----
    for (int idx = tid; idx < 51 * G4; idx += NTHREADS) {
        int k = idx >> 8, c = idx & 255;
        int jj = c >> 2, g = c & 3;
        float v = 0.f;
        if (jj < HDIM) {
            if (k < HDIM)      v = W_hh[(g * HDIM + jj) * HDIM + k];
            else               v = W_ih[g * HDIM + jj];          // row 50
        }
        Ws[idx] = v;
    }
    for (int idx = tid; idx < G4; idx += NTHREADS) {
        int jj = idx >> 2, g = idx & 3;
        bbv[idx] = (jj < HDIM) ? (b_ih[g * HDIM + jj] + b_hh[g * HDIM + jj]) : 0.f;
    }
    for (int idx = tid; idx < 2 * HBUF; idx += NTHREADS) hb[idx] = 0.f;
    // prefill x tile 0 (buffer 0): coalesced read, transposed store
    for (int idx = tid; idx < 32 * 32; idx += NTHREADS) {
        int ss = idx >> 5, tt = idx & 31;
        xs[tt * XROW + ss] = x[(bbase + ss) * TSTEPS + tt];
    }
    __syncthreads();

    // ---- 4-phase stagger: cohort c starts c * (~1100 cyc) late so the four
    // MUFU epilogues are evenly spread through each step on every SMSP ----
    {
        int iters = coh * 275;
        float z = 0.f;
        #pragma unroll 1
        for (int i = 0; i < iters; i++)
            asm volatile("add.f32 %0, %0, 0f3F800000;" : "+f"(z));
        if (z < 0.f) sm[OFF_PAD + lane] = z;   // opaque sink, never taken
    }

    // persistent packed biases / W_ih for this thread's 4 gate columns
    float4 b4 = *(const float4*)(bbv + 4 * j);
    ull bbg[4] = { pack2(b4.x, b4.x), pack2(b4.y, b4.y),
                   pack2(b4.z, b4.z), pack2(b4.w, b4.w) };
    float4 xw4 = *(const float4*)(Ws + 50 * G4 + 4 * j);
    ull xwg[4] = { pack2(xw4.x, xw4.x), pack2(xw4.y, xw4.y),
                   pack2(xw4.z, xw4.z), pack2(xw4.w, xw4.w) };

    float c_st[4];
    #pragma unroll
    for (int i = 0; i < 4; i++) c_st[i] = 0.f;

    int buf = 0;

    for (int t = 0; t < TSTEPS; t++) {
        cohort_bar(bid);               // this cohort's prev-step h writes (+ x refill) visible

        // refill next x tile for THIS COHORT's 8 samples only
        if ((t & 31) == 0 && t + 32 < TSTEPS) {
            float* xd = xs + (((t >> 5) & 1) ^ 1) * XBUF;
            for (int idx = ctid; idx < 8 * 32; idx += 128) {
                int ss = 8 * coh + (idx >> 5), tt = idx & 31;
                xd[tt * XROW + ss] = x[(bbase + ss) * TSTEPS + t + 32 + tt];
            }
        }

        const float* hB   = hb + buf * HBUF;
        const float* xrow = xs + ((t >> 5) & 1) * XBUF + (t & 31) * XROW + sb;

        ull acc[4][2];                 // [gate][sample-pair]
        #pragma unroll
        for (int g = 0; g < 4; g++) {
            acc[g][0] = bbg[g];
            acc[g][1] = bbg[g];
        }

        #pragma unroll 10
        for (int k = 0; k < 50; k++) {
            // predicated dense LDS.128: invalid lanes (j>=50) generate no wavefronts
            float4 w4 = make_float4(0.f, 0.f, 0.f, 0.f);
            if (jv) w4 = *(const float4*)(Ws + k * G4 + 4 * j);
            ull wg[4] = { pack2(w4.x, w4.x), pack2(w4.y, w4.y),
                          pack2(w4.z, w4.z), pack2(w4.w, w4.w) };
            const float* hr = hB + k * HROW + sb;                // 16B aligned
            ulonglong2 hq = *(const ulonglong2*)(hr);            // bcast: (h0,h1),(h2,h3)
            #pragma unroll
            for (int g = 0; g < 4; g++) {
                acc[g][0] = fma2(hq.x, wg[g], acc[g][0]);
                acc[g][1] = fma2(hq.y, wg[g], acc[g][1]);
            }
        }
        // x contribution (row 50 weights persistent in registers)
        {
            ulonglong2 xq = *(const ulonglong2*)(xrow);
            #pragma unroll
            for (int g = 0; g < 4; g++) {
                acc[g][0] = fma2(xq.x, xwg[g], acc[g][0]);
                acc[g][1] = fma2(xq.y, xwg[g], acc[g][1]);
            }
        }

        // ---- gates: this thread = unit j, samples sb..sb+3 (fast tanh path) ----
        float* hn = hb + (buf ^ 1) * HBUF + j * HROW + sb;
        float hv[4];
        #pragma unroll
        for (int p = 0; p < 2; p++) {
            float zi0, zi1, zf0, zf1, zg0, zg1, zo0, zo1;
            unpack2(acc[0][p], zi0, zi1);
            unpack2(acc[1][p], zf0, zf1);
            unpack2(acc[2][p], zg0, zg1);
            unpack2(acc[3][p], zo0, zo1);
            float i0 = sigmoid_fast(zi0), i1 = sigmoid_fast(zi1);
            float f0 = sigmoid_fast(zf0), f1 = sigmoid_fast(zf1);
            float g0 = tanh_fast(zg0),    g1 = tanh_fast(zg1);
            float o0 = sigmoid_fast(zo0), o1 = sigmoid_fast(zo1);
            float c0 = fmaf(f0, c_st[2*p],   i0 * g0);
            float c1 = fmaf(f1, c_st[2*p+1], i1 * g1);
            c_st[2*p]   = c0;
            c_st[2*p+1] = c1;
            hv[2*p]   = o0 * tanh_fast(c0);
            hv[2*p+1] = o1 * tanh_fast(c1);
        }
        if (jv) {
            *(float4*)hn = make_float4(hv[0], hv[1], hv[2], hv[3]);  // STS.128, conflict-free
        }
        buf ^= 1;
    }

    __syncthreads();   // all cohorts' final h visible

    // ---------------- quantum head: 1 thread per sample (exact math) ----------------
    if (tid < SAMPLES) {
        const float* hfin = hb + buf * HBUF + tid;   // h[k][tid] at stride HROW

        float ang[4];
        #pragma unroll
        for (int w = 0; w < 4; w++) {
            float a = bp[w];
            for (int k = 0; k < HDIM; k++) a = fmaf(Wp[w * HDIM + k], hfin[k * HROW], a);
            ang[w] = tanhf_(a) * 1.5707963267948966f;
        }

        float re[16], im[16];
        #pragma unroll
        for (int i = 0; i < 16; i++) { re[i] = 0.f; im[i] = 0.f; }
        re[0] = 1.f;

        // RX embedding (wire w <-> bit 3-w)
        #pragma unroll
        for (int w = 0; w < 4; w++) {
            float sw, cw;
            sincosf(0.5f * ang[w], &sw, &cw);
            const int m = 8 >> w;
            #pragma unroll
            for (int i0 = 0; i0 < 16; i0++) {
                if (!(i0 & m)) {
                    int i1 = i0 | m;
                    float r0 = re[i0], q0 = im[i0], r1 = re[i1], q1 = im[i1];
                    re[i0] = cw * r0 + sw * q1;  im[i0] = cw * q0 - sw * r1;
                    re[i1] = cw * r1 + sw * q0;  im[i1] = cw * q1 - sw * r0;
                }
            }
        }

        // StronglyEntanglingLayers
        #pragma unroll
        for (int l = 0; l < 2; l++) {
            #pragma unroll
            for (int w = 0; w < 4; w++) {
                const float* q = qw + (l * 4 + w) * 3;
                float phi = q[0], th = q[1], om = q[2];
                float st_, ct_; sincosf(0.5f * th, &st_, &ct_);
                float sa, ca;   sincosf(0.5f * (phi + om), &sa, &ca);
                float sb2, cb2; sincosf(0.5f * (phi - om), &sb2, &cb2);
                float u00r =  ct_ * ca,  u00i = -ct_ * sa;
                float u01r = -st_ * cb2, u01i = -st_ * sb2;
                float u10r =  st_ * cb2, u10i = -st_ * sb2;
                float u11r =  ct_ * ca,  u11i =  ct_ * sa;
                const int m = 8 >> w;
                #pragma unroll
                for (int i0 = 0; i0 < 16; i0++) {
                    if (!(i0 & m)) {
                        int i1 = i0 | m;
                        float r0 = re[i0], q0 = im[i0], r1 = re[i1], q1 = im[i1];
                        re[i0] = u00r*r0 - u00i*q0 + u01r*r1 - u01i*q1;
                        im[i0] = u00r*q0 + u00i*r0 + u01r*q1 + u01i*r1;
                        re[i1] = u10r*r0 - u10i*q0 + u11r*r1 - u11i*q1;
                        im[i1] = u10r*q0 + u10i*r0 + u11r*q1 + u11i*r1;
                    }
                }
            }
            const int r = (l % 3) + 1;
            #pragma unroll
            for (int w = 0; w < 4; w++) {
                const int cm = 8 >> w;
                const int tm = 8 >> ((w + r) & 3);
                #pragma unroll
                for (int i0 = 0; i0 < 16; i0++) {
                    if ((i0 & cm) && !(i0 & tm)) {
                        int i1 = i0 | tm;
                        float tr = re[i0]; re[i0] = re[i1]; re[i1] = tr;
                        float ti = im[i0]; im[i0] = im[i1]; im[i1] = ti;
                    }
                }
            }
        }

        float o = bo[0];
        #pragma unroll
        for (int w = 0; w < 4; w++) {
            const int m = 8 >> w;
            float ev = 0.f;
            #pragma unroll
            for (int i = 0; i < 16; i++) {
                float p = re[i] * re[i] + im[i] * im[i];
                ev += (i & m) ? -p : p;
            }
            o = fmaf(Wo[w], ev, o);
        }
        out[bbase + tid] = o;
    }
}

extern "C" void kernel_launch(void* const* d_in, const int* in_sizes, int n_in,
                              void* d_out, int out_size) {
    const float* x    = (const float*)d_in[0];
    const float* W_ih = (const float*)d_in[1];
    const float* W_hh = (const float*)d_in[2];
    const float* b_ih = (const float*)d_in[3];
    const float* b_hh = (const float*)d_in[4];
    const float* Wp   = (const float*)d_in[5];
    const float* bp   = (const float*)d_in[6];
    const float* qw   = (const float*)d_in[7];
    const float* Wo   = (const float*)d_in[8];
    const float* bo   = (const float*)d_in[9];
    float* out = (float*)d_out;

    const size_t smem = SMEM_FLOATS * sizeof(float);
    cudaFuncSetAttribute(lstm_q_kernel, cudaFuncAttributeMaxDynamicSharedMemorySize, (int)smem);

    lstm_q_kernel<<<4096 / SAMPLES, NTHREADS, smem>>>(
        x, W_ih, W_hh, b_ih, b_hh, Wp, bp, qw, Wo, bo, out);
}

// round 17
// speedup vs baseline: 1.4560x; 1.4560x over previous
#include <cuda_runtime.h>
#include <cuda_bf16.h>
#include <cstdint>

#define NTHREADS 256
#define SAMPLES  32
#define HDIM     50
#define TSTEPS   256
#define KDIM     64
#define BSTR     72            // bf16 per B row (144 B) — ldmatrix conflict-free
#define ZSTR     268           // Z[s][m] float stride — STS/LDS conflict-free
#define HFSTR    36

// smem byte layout
#define SM_BHI   0
#define SM_BLO   4608          // 32*144
#define SM_Z     9216          // 32*268*4 = 34304
#define SM_AST   9216          // A staging (init only, 256*144 = 36864) overlaps Z+HFIN
#define SM_HFIN  43520         // 50*36*4 = 7200
#define SM_BYTES 50720

typedef uint32_t u32;

__device__ __forceinline__ u32 smem_u32(const void* p) {
    u32 a;
    asm("{ .reg .u64 t; cvta.to.shared.u64 t, %1; cvt.u32.u64 %0, t; }" : "=r"(a) : "l"(p));
    return a;
}
__device__ __forceinline__ void ldm_x4(u32& r0, u32& r1, u32& r2, u32& r3, u32 addr) {
    asm volatile("ldmatrix.sync.aligned.m8n8.x4.shared.b16 {%0,%1,%2,%3}, [%4];"
                 : "=r"(r0), "=r"(r1), "=r"(r2), "=r"(r3) : "r"(addr));
}
__device__ __forceinline__ void ldm_x2(u32& r0, u32& r1, u32 addr) {
    asm volatile("ldmatrix.sync.aligned.m8n8.x2.shared.b16 {%0,%1}, [%2];"
                 : "=r"(r0), "=r"(r1) : "r"(addr));
}
__device__ __forceinline__ void mma_bf16(float& c0, float& c1, float& c2, float& c3,
                                         u32 a0, u32 a1, u32 a2, u32 a3,
                                         u32 b0, u32 b1) {
    asm volatile("mma.sync.aligned.m16n8k16.row.col.f32.bf16.bf16.f32 "
                 "{%0,%1,%2,%3}, {%4,%5,%6,%7}, {%8,%9}, {%0,%1,%2,%3};"
                 : "+f"(c0), "+f"(c1), "+f"(c2), "+f"(c3)
                 : "r"(a0), "r"(a1), "r"(a2), "r"(a3), "r"(b0), "r"(b1));
}
__device__ __forceinline__ float tanh_fast(float x) {
    float y; asm("tanh.approx.f32 %0, %1;" : "=f"(y) : "f"(x)); return y;
}
__device__ __forceinline__ float sigmoid_fast(float x) {
    return fmaf(0.5f, tanh_fast(0.5f * x), 0.5f);
}
__device__ __forceinline__ float sigmoidf_(float x) {
    return __fdividef(1.f, 1.f + __expf(-x));
}
__device__ __forceinline__ float tanhf_(float x) {
    return fmaf(2.f, sigmoidf_(2.f * x), -1.f);
}
__device__ __forceinline__ void store_split(char* bhi, char* blo, int s, int k, float v) {
    __nv_bfloat16 h = __float2bfloat16(v);
    float r = v - __bfloat162float(h);
    __nv_bfloat16 l = __float2bfloat16(r);
    *(unsigned short*)(bhi + s * 144 + 2 * k) = __bfloat16_as_ushort(h);
    *(unsigned short*)(blo + s * 144 + 2 * k) = __bfloat16_as_ushort(l);
}

__global__ void __launch_bounds__(NTHREADS, 1) lstm_q_kernel(
    const float* __restrict__ x,    const float* __restrict__ W_ih,
    const float* __restrict__ W_hh, const float* __restrict__ b_ih,
    const float* __restrict__ b_hh, const float* __restrict__ Wp,
    const float* __restrict__ bp,   const float* __restrict__ qw,
    const float* __restrict__ Wo,   const float* __restrict__ bo,
    float* __restrict__ out)
{
    extern __shared__ char smem[];
    char*  bhi  = smem + SM_BHI;
    char*  blo  = smem + SM_BLO;
    float* Zf   = (float*)(smem + SM_Z);
    float* hfin = (float*)(smem + SM_HFIN);
    const u32 sb_bhi = smem_u32(bhi);
    const u32 sb_blo = smem_u32(blo);
    const u32 sb_ast = smem_u32(smem + SM_AST);

    const int tid   = threadIdx.x;
    const int lane  = tid & 31;
    const int warp  = tid >> 5;
    const int bbase = blockIdx.x * SAMPLES;

    // ---- B init: zeros, bias-one col 51, x_0 col 50 ----
    for (int i = tid; i < 1152; i += NTHREADS) ((u32*)bhi)[i] = 0;  // 4608B
    for (int i = tid; i < 1152; i += NTHREADS) ((u32*)blo)[i] = 0;
    __syncthreads();
    if (tid < SAMPLES) {
        store_split(bhi, blo, tid, 51, 1.0f);
        store_split(bhi, blo, tid, 50, x[(bbase + tid) * TSTEPS + 0]);
    }

    // ---- stage W (hi), ldmatrix persistent A fragments; then lo ----
    // A[m][k]: m = 4j+g; k<50 = W_hh, 50 = W_ih, 51 = bias, else 0
    u32 Ah[2][4][4], Al[2][4][4];
    for (int pass = 0; pass < 2; pass++) {
        for (int idx = tid; idx < 256 * KDIM; idx += NTHREADS) {
            int m = idx >> 6, k = idx & 63;
            int j = m >> 2, g = m & 3;
            float v = 0.f;
            if (j < HDIM) {
                if (k < HDIM)      v = W_hh[(g * HDIM + j) * HDIM + k];
                else if (k == 50)  v = W_ih[g * HDIM + j];
                else if (k == 51)  v = b_ih[g * HDIM + j] + b_hh[g * HDIM + j];
            }
            __nv_bfloat16 h = __float2bfloat16(v);
            unsigned short bits;
            if (pass == 0) bits = __bfloat16_as_ushort(h);
            else           bits = __bfloat16_as_ushort(__float2bfloat16(v - __bfloat162float(h)));
            *(unsigned short*)(smem + SM_AST + m * 144 + 2 * k) = bits;
        }
        __syncthreads();
        #pragma unroll
        for (int mt = 0; mt < 2; mt++) {
            #pragma unroll
            for (int kt = 0; kt < 4; kt++) {
                int q = lane >> 3;
                int row = 32 * warp + mt * 16 + (q & 1) * 8 + (lane & 7);
                int col = kt * 16 + (q >> 1) * 8;
                u32 addr = sb_ast + row * 144 + col * 2;
                if (pass == 0) ldm_x4(Ah[mt][kt][0], Ah[mt][kt][1], Ah[mt][kt][2], Ah[mt][kt][3], addr);
                else           ldm_x4(Al[mt][kt][0], Al[mt][kt][1], Al[mt][kt][2], Al[mt][kt][3], addr);
            }
        }
        __syncthreads();
    }

    // epilogue mapping (R14): unit j, samples sbs..sbs+7
    const int ug  = warp & 1;
    const int j   = 32 * ug + lane;
    const int sg  = warp >> 1;             // 0..3
    const int sbs = 8 * sg;
    const bool jv = (j < HDIM);

    float c_st[8];
    #pragma unroll
    for (int i = 0; i < 8; i++) c_st[i] = 0.f;

    for (int t = 0; t < TSTEPS; t++) {
        __syncthreads();     // h (B tiles) from prev epilogue visible

        float xnext = 0.f;
        if (warp == 0 && t + 1 < TSTEPS) xnext = x[(bbase + lane) * TSTEPS + t + 1];

        // ---- GEMM: acc[mt][nt][4] = A * B ----
        float ac[2][4][4];
        #pragma unroll
        for (int mt = 0; mt < 2; mt++)
            #pragma unroll
            for (int nt = 0; nt < 4; nt++)
                #pragma unroll
                for (int i = 0; i < 4; i++) ac[mt][nt][i] = 0.f;

        #pragma unroll
        for (int kt = 0; kt < 4; kt++) {
            int r = lane & 15;
            int row_n = (r & 7);
            int k0 = kt * 16 + ((r >> 3) & 1) * 8;
            u32 bh[4][2], bl[4][2];
            #pragma unroll
            for (int nt = 0; nt < 4; nt++) {
                u32 boff = (nt * 8 + row_n) * 144 + k0 * 2;
                ldm_x2(bh[nt][0], bh[nt][1], sb_bhi + boff);
                ldm_x2(bl[nt][0], bl[nt][1], sb_blo + boff);
            }
            #pragma unroll
            for (int mt = 0; mt < 2; mt++) {
                #pragma unroll
                for (int nt = 0; nt < 4; nt++) {
                    mma_bf16(ac[mt][nt][0], ac[mt][nt][1], ac[mt][nt][2], ac[mt][nt][3],
                             Ah[mt][kt][0], Ah[mt][kt][1], Ah[mt][kt][2], Ah[mt][kt][3],
                             bh[nt][0], bh[nt][1]);
                    mma_bf16(ac[mt][nt][0], ac[mt][nt][1], ac[mt][nt][2], ac[mt][nt][3],
                             Al[mt][kt][0], Al[mt][kt][1], Al[mt][kt][2], Al[mt][kt][3],
                             bh[nt][0], bh[nt][1]);
                    mma_bf16(ac[mt][nt][0], ac[mt][nt][1], ac[mt][nt][2], ac[mt][nt][3],
                             Ah[mt][kt][0], Ah[mt][kt][1], Ah[mt][kt][2], Ah[mt][kt][3],
                             bl[nt][0], bl[nt][1]);
                }
            }
        }

        // ---- scatter Z to smem: Z[s][m], stride 268 (conflict-free) ----
        #pragma unroll
        for (int mt = 0; mt < 2; mt++) {
            #pragma unroll
            for (int nt = 0; nt < 4; nt++) {
                #pragma unroll
                for (int i = 0; i < 4; i++) {
                    int row = 32 * warp + mt * 16 + (lane >> 2) + (i >> 1) * 8;
                    int s   = nt * 8 + 2 * (lane & 3) + (i & 1);
                    Zf[s * ZSTR + row] = ac[mt][nt][i];
                }
            }
        }
        __syncthreads();     // Z complete; B reads done -> epilogue may overwrite B

        // ---- gate epilogue: unit j, samples sbs..sbs+7 ----
        #pragma unroll
        for (int p = 0; p < 8; p++) {
            float4 z4 = *(const float4*)(Zf + (sbs + p) * ZSTR + 4 * j);
            float ig = sigmoid_fast(z4.x);
            float fg = sigmoid_fast(z4.y);
            float gg = tanh_fast(z4.z);
            float og = sigmoid_fast(z4.w);
            float c  = fmaf(fg, c_st[p], ig * gg);
            c_st[p]  = c;
            float hv = og * tanh_fast(c);
            if (jv) {
                store_split(bhi, blo, sbs + p, j, hv);
                if (t == TSTEPS - 1) hfin[j * HFSTR + sbs + p] = hv;
            }
        }
        if (warp == 0 && t + 1 < TSTEPS) store_split(bhi, blo, lane, 50, xnext);
    }

    __syncthreads();

    // ---------------- quantum head: 1 thread per sample (exact math) ----------------
    if (tid < SAMPLES) {
        float ang[4];
        #pragma unroll
        for (int w = 0; w < 4; w++) {
            float a = bp[w];
            for (int k = 0; k < HDIM; k++) a = fmaf(Wp[w * HDIM + k], hfin[k * HFSTR + tid], a);
            ang[w] = tanhf_(a) * 1.5707963267948966f;
        }

        float re[16], im[16];
        #pragma unroll
        for (int i = 0; i < 16; i++) { re[i] = 0.f; im[i] = 0.f; }
        re[0] = 1.f;

        #pragma unroll
        for (int w = 0; w < 4; w++) {
            float sw, cw;
            sincosf(0.5f * ang[w], &sw, &cw);
            const int m = 8 >> w;
            #pragma unroll
            for (int i0 = 0; i0 < 16; i0++) {
                if (!(i0 & m)) {
                    int i1 = i0 | m;
                    float r0 = re[i0], q0 = im[i0], r1 = re[i1], q1 = im[i1];
                    re[i0] = cw * r0 + sw * q1;  im[i0] = cw * q0 - sw * r1;
                    re[i1] = cw * r1 + sw * q0;  im[i1] = cw * q1 - sw * r0;
                }
            }
        }

        #pragma unroll
        for (int l = 0; l < 2; l++) {
            #pragma unroll
            for (int w = 0; w < 4; w++) {
                const float* q = qw + (l * 4 + w) * 3;
                float phi = q[0], th = q[1], om = q[2];
                float st_, ct_; sincosf(0.5f * th, &st_, &ct_);
                float sa, ca;   sincosf(0.5f * (phi + om), &sa, &ca);
                float sb2, cb2; sincosf(0.5f * (phi - om), &sb2, &cb2);
                float u00r =  ct_ * ca,  u00i = -ct_ * sa;
                float u01r = -st_ * cb2, u01i = -st_ * sb2;
                float u10r =  st_ * cb2, u10i = -st_ * sb2;
                float u11r =  ct_ * ca,  u11i =  ct_ * sa;
                const int m = 8 >> w;
                #pragma unroll
                for (int i0 = 0; i0 < 16; i0++) {
                    if (!(i0 & m)) {
                        int i1 = i0 | m;
                        float r0 = re[i0], q0 = im[i0], r1 = re[i1], q1 = im[i1];
                        re[i0] = u00r*r0 - u00i*q0 + u01r*r1 - u01i*q1;
                        im[i0] = u00r*q0 + u00i*r0 + u01r*q1 + u01i*r1;
                        re[i1] = u10r*r0 - u10i*q0 + u11r*r1 - u11i*q1;
                        im[i1] = u10r*q0 + u10i*r0 + u11r*q1 + u11i*r1;
                    }
                }
            }
            const int r = (l % 3) + 1;
            #pragma unroll
            for (int w = 0; w < 4; w++) {
                const int cm = 8 >> w;
                const int tm = 8 >> ((w + r) & 3);
                #pragma unroll
                for (int i0 = 0; i0 < 16; i0++) {
                    if ((i0 & cm) && !(i0 & tm)) {
                        int i1 = i0 | tm;
                        float tr = re[i0]; re[i0] = re[i1]; re[i1] = tr;
                        float ti = im[i0]; im[i0] = im[i1]; im[i1] = ti;
                    }
                }
            }
        }

        float o = bo[0];
        #pragma unroll
        for (int w = 0; w < 4; w++) {
            const int m = 8 >> w;
            float ev = 0.f;
            #pragma unroll
            for (int i = 0; i < 16; i++) {
                float p = re[i] * re[i] + im[i] * im[i];
                ev += (i & m) ? -p : p;
            }
            o = fmaf(Wo[w], ev, o);
        }
        out[bbase + tid] = o;
    }
}

extern "C" void kernel_launch(void* const* d_in, const int* in_sizes, int n_in,
                              void* d_out, int out_size) {
    const float* x    = (const float*)d_in[0];
    const float* W_ih = (const float*)d_in[1];
    const float* W_hh = (const float*)d_in[2];
    const float* b_ih = (const float*)d_in[3];
    const float* b_hh = (const float*)d_in[4];
    const float* Wp   = (const float*)d_in[5];
    const float* bp   = (const float*)d_in[6];
    const float* qw   = (const float*)d_in[7];
    const float* Wo   = (const float*)d_in[8];
    const float* bo   = (const float*)d_in[9];
    float* out = (float*)d_out;

    cudaFuncSetAttribute(lstm_q_kernel, cudaFuncAttributeMaxDynamicSharedMemorySize, SM_BYTES);
    lstm_q_kernel<<<4096 / SAMPLES, NTHREADS, SM_BYTES>>>(
        x, W_ih, W_hh, b_ih, b_hh, Wp, bp, qw, Wo, bo, out);
}